// round 16
// baseline (speedup 1.0000x reference)
#include <cuda_runtime.h>
#include <math.h>

#define N_NODES 100000
#define NE      1600000
#define H1H     8
#define C1C     16
#define D1      128
#define NC      40
#define NEG     0.2f

// Scratch: __device__ globals referenced ONLY inside device code (GB300 ATS
// trap: passing the symbol as a kernel arg from host passes the host shadow).
__device__ __align__(256) float g_h1[N_NODES * D1];
__device__ __align__(256) float g_hrelu[N_NODES * D1];
__device__ __align__(256) float g_h2[N_NODES * NC];
__device__ __align__(256) float g_ssrc1[N_NODES * H1H];
__device__ __align__(256) float g_sdst1[N_NODES * H1H];
__device__ __align__(256) float g_ssrc2[N_NODES];
__device__ __align__(256) float g_sdst2[N_NODES];
__device__ __align__(256) int   g_deg[N_NODES];
__device__ __align__(256) int   g_cur[N_NODES];
__device__ __align__(256) int   g_off[N_NODES + 1];
__device__ __align__(256) int   g_srt[NE];

#define SCAN_B 1024
#define NSB ((N_NODES + SCAN_B - 1) / SCAN_B)   /* 98 */
__device__ __align__(256) int g_part[NSB];

__device__ __forceinline__ float lrelu(float x) { return x > 0.f ? x : NEG * x; }

// ---- CSR build (edge_index: int32 planar) ----
__global__ void k_zero() {
    int i = blockIdx.x * blockDim.x + threadIdx.x;
    if (i < N_NODES) { g_deg[i] = 0; g_cur[i] = 0; }
}
__global__ void k_hist(const int* __restrict__ ei) {
    int e = blockIdx.x * blockDim.x + threadIdx.x;
    if (e < NE) atomicAdd(&g_deg[ei[NE + e]], 1);
}
__global__ void k_scan1() {
    __shared__ int s[SCAN_B];
    int t = threadIdx.x, i = blockIdx.x * SCAN_B + t;
    int v = (i < N_NODES) ? g_deg[i] : 0;
    s[t] = v; __syncthreads();
    for (int d = 1; d < SCAN_B; d <<= 1) {
        int x = (t >= d) ? s[t - d] : 0; __syncthreads();
        s[t] += x; __syncthreads();
    }
    if (i < N_NODES) g_off[i] = s[t] - v;
    if (t == SCAN_B - 1) g_part[blockIdx.x] = s[t];
}
__global__ void k_scan2() {
    __shared__ int s[128];
    int t = threadIdx.x;
    int v = (t < NSB) ? g_part[t] : 0;
    s[t] = v; __syncthreads();
    for (int d = 1; d < 128; d <<= 1) {
        int x = (t >= d) ? s[t - d] : 0; __syncthreads();
        s[t] += x; __syncthreads();
    }
    if (t < NSB) g_part[t] = s[t] - v;
}
__global__ void k_scan3() {
    int i = blockIdx.x * blockDim.x + threadIdx.x;
    if (i < N_NODES) g_off[i] += g_part[i >> 10];
    if (i == 0) g_off[N_NODES] = NE;
}
__global__ void k_scatter(const int* __restrict__ ei) {
    int e = blockIdx.x * blockDim.x + threadIdx.x;
    if (e < NE) {
        int d = ei[NE + e];
        int pos = g_off[d] + atomicAdd(&g_cur[d], 1);
        g_srt[pos] = ei[e];
    }
}

// ---- GEMM1 (BK=32, double-buffered smem) + fused s1 logits ----
// dyn smem: As[2][32][132] then Bs[2][32][132] floats = 67584 B
#define G1_SMEM 67584

__global__ void __launch_bounds__(256)
k_gemm1s(const float* __restrict__ A, const float* __restrict__ B,
         const float* __restrict__ as1, const float* __restrict__ ad1) {
    extern __shared__ float sm[];
    float* AsB = sm;            // [2][32][132]
    float* BsB = sm + 8448;     // [2][32][132]
    int tid = threadIdx.x, tx = tid & 15, ty = tid >> 4;
    int row0 = blockIdx.x * 128, r0 = ty * 8, c0 = tx * 8;

    float acc[8][8];
#pragma unroll
    for (int i = 0; i < 8; i++)
#pragma unroll
        for (int j = 0; j < 8; j++) acc[i][j] = 0.f;

    // tile loader: chunk at kb into buffer b
    auto load_tile = [&](int b, int kb) {
        float* As = AsB + b * 4224;
        float* Bs = BsB + b * 4224;
#pragma unroll
        for (int q = 0; q < 4; q++) {
            int f = tid + 256 * q;          // 0..1023 float4 slots (A)
            int r = f >> 3, c4 = f & 7;
            int row = row0 + r;
            float4 v = (row < N_NODES)
                       ? *(const float4*)&A[row * 128 + kb + c4 * 4]
                       : make_float4(0.f, 0.f, 0.f, 0.f);
            As[(c4 * 4 + 0) * 132 + r] = v.x;
            As[(c4 * 4 + 1) * 132 + r] = v.y;
            As[(c4 * 4 + 2) * 132 + r] = v.z;
            As[(c4 * 4 + 3) * 132 + r] = v.w;
        }
#pragma unroll
        for (int q = 0; q < 4; q++) {
            int f = tid + 256 * q;          // (B)
            int kk = f >> 5, c4 = f & 31;
            *(float4*)&Bs[kk * 132 + c4 * 4] = *(const float4*)&B[(kb + kk) * 128 + c4 * 4];
        }
    };

    load_tile(0, 0);
    __syncthreads();
#pragma unroll
    for (int c = 0; c < 4; c++) {
        int cur = c & 1;
        if (c < 3) load_tile(1 - cur, (c + 1) * 32);   // LDGs overlap compute
        const float* As = AsB + cur * 4224;
        const float* Bs = BsB + cur * 4224;
#pragma unroll
        for (int kk = 0; kk < 32; kk++) {
            float a[8], b[8];
#pragma unroll
            for (int i = 0; i < 8; i++) a[i] = As[kk * 132 + r0 + i];
#pragma unroll
            for (int j = 0; j < 8; j++) b[j] = Bs[kk * 132 + c0 + j];
#pragma unroll
            for (int i = 0; i < 8; i++)
#pragma unroll
                for (int j = 0; j < 8; j++) acc[i][j] += a[i] * b[j];
        }
        __syncthreads();
    }

    // epilogue: write h1 + fused s1 partial dots
    int h = tx >> 1;
    int cb = h * C1C + (tx & 1) * 8;
    float av[8], dv[8];
#pragma unroll
    for (int j = 0; j < 8; j++) { av[j] = as1[cb + j]; dv[j] = ad1[cb + j]; }

#pragma unroll
    for (int i = 0; i < 8; i++) {
        int row = row0 + r0 + i;
        if (row >= N_NODES) continue;
        *(float4*)&g_h1[row * 128 + c0]     = make_float4(acc[i][0], acc[i][1], acc[i][2], acc[i][3]);
        *(float4*)&g_h1[row * 128 + c0 + 4] = make_float4(acc[i][4], acc[i][5], acc[i][6], acc[i][7]);
        float ps = 0.f, pd = 0.f;
#pragma unroll
        for (int j = 0; j < 8; j++) { ps += acc[i][j] * av[j]; pd += acc[i][j] * dv[j]; }
        ps += __shfl_xor_sync(0xffffffffu, ps, 1);
        pd += __shfl_xor_sync(0xffffffffu, pd, 1);
        if ((tx & 1) == 0) {
            g_ssrc1[row * H1H + h] = ps;
            g_sdst1[row * H1H + h] = pd;
        }
    }
}

// ---- GEMM2 + fused s2 logits ----
__global__ void k_gemm2s(const float* __restrict__ B,
                         const float* __restrict__ as2, const float* __restrict__ ad2) {
    __shared__ float As[16][132];
    __shared__ float Bs[16][48];
    int tid = threadIdx.x, tx = tid & 15, ty = tid >> 4;
    int row0 = blockIdx.x * 128, r0 = ty * 8;
    float acc[8][3];
#pragma unroll
    for (int i = 0; i < 8; i++)
#pragma unroll
        for (int j = 0; j < 3; j++) acc[i][j] = 0.f;
    for (int kb = 0; kb < 128; kb += 16) {
        for (int l = tid; l < 2048; l += 256) {
            int r = l >> 4, kk = l & 15, row = row0 + r;
            As[kk][r] = (row < N_NODES) ? g_hrelu[row * 128 + kb + kk] : 0.f;
        }
        for (int l = tid; l < 640; l += 256) {
            int kk = l / 40, col = l % 40;
            Bs[kk][col] = B[(kb + kk) * 40 + col];
        }
        __syncthreads();
#pragma unroll
        for (int kk = 0; kk < 16; kk++) {
            float a[8];
#pragma unroll
            for (int i = 0; i < 8; i++) a[i] = As[kk][r0 + i];
            float b0 = Bs[kk][tx], b1 = Bs[kk][tx + 16], b2 = (tx < 8) ? Bs[kk][tx + 32] : 0.f;
#pragma unroll
            for (int i = 0; i < 8; i++) {
                acc[i][0] += a[i] * b0; acc[i][1] += a[i] * b1; acc[i][2] += a[i] * b2;
            }
        }
        __syncthreads();
    }
    float a0 = as2[tx], a1 = as2[tx + 16], a2 = (tx < 8) ? as2[tx + 32] : 0.f;
    float d0 = ad2[tx], d1 = ad2[tx + 16], d2 = (tx < 8) ? ad2[tx + 32] : 0.f;
#pragma unroll
    for (int i = 0; i < 8; i++) {
        int row = row0 + r0 + i;
        if (row >= N_NODES) continue;
        g_h2[row * 40 + tx] = acc[i][0];
        g_h2[row * 40 + tx + 16] = acc[i][1];
        if (tx < 8) g_h2[row * 40 + tx + 32] = acc[i][2];
        float ps = acc[i][0] * a0 + acc[i][1] * a1 + acc[i][2] * a2;
        float pd = acc[i][0] * d0 + acc[i][1] * d1 + acc[i][2] * d2;
#pragma unroll
        for (int o = 8; o; o >>= 1) {
            ps += __shfl_xor_sync(0xffffffffu, ps, o);
            pd += __shfl_xor_sync(0xffffffffu, pd, o);
        }
        if (tx == 0) { g_ssrc2[row] = ps; g_sdst2[row] = pd; }
    }
}

// ---- layer1 aggregation: warp/node, single-pass online softmax ----
__global__ void k_agg1(const float* __restrict__ b1) {
    int warp = (blockIdx.x * blockDim.x + threadIdx.x) >> 5;
    int lane = threadIdx.x & 31;
    if (warp >= N_NODES) return;
    int i = warp, h = lane >> 2;
    float sdst = g_sdst1[i * H1H + h];
    float m = lrelu(g_ssrc1[i * H1H + h] + sdst);
    int beg = g_off[i], end = g_off[i + 1];
    const float4* hp = (const float4*)g_h1;
    float den = 1.f;
    float4 acc = hp[i * 32 + lane];
    int s = (beg < end) ? g_srt[beg] : 0;
    for (int j = beg; j < end; j++) {
        int snext = (j + 1 < end) ? g_srt[j + 1] : 0;
        float e = lrelu(g_ssrc1[s * H1H + h] + sdst);
        float p;
        if (e > m) {
            float sc = __expf(m - e);
            den *= sc;
            acc.x *= sc; acc.y *= sc; acc.z *= sc; acc.w *= sc;
            m = e; p = 1.f;
        } else {
            p = __expf(e - m);
        }
        float4 w = hp[s * 32 + lane];
        den += p;
        acc.x += p * w.x; acc.y += p * w.y; acc.z += p * w.z; acc.w += p * w.w;
        s = snext;
    }
    float inv = 1.f / den;
    float4 o;
    o.x = fmaxf(acc.x * inv + b1[lane * 4 + 0], 0.f);
    o.y = fmaxf(acc.y * inv + b1[lane * 4 + 1], 0.f);
    o.z = fmaxf(acc.z * inv + b1[lane * 4 + 2], 0.f);
    o.w = fmaxf(acc.w * inv + b1[lane * 4 + 3], 0.f);
    ((float4*)g_hrelu)[i * 32 + lane] = o;
}

// ---- layer2 aggregation (online softmax) + log_softmax ----
__global__ void k_agg2(const float* __restrict__ b2, float* __restrict__ out) {
    int warp = (blockIdx.x * blockDim.x + threadIdx.x) >> 5;
    int lane = threadIdx.x & 31;
    if (warp >= N_NODES) return;
    int i = warp;
    float sdst = g_sdst2[i];
    float m = lrelu(g_ssrc2[i] + sdst);
    int beg = g_off[i], end = g_off[i + 1];
    float den = 1.f;
    float a0 = g_h2[i * NC + lane];
    float a1 = (lane < 8) ? g_h2[i * NC + 32 + lane] : 0.f;
    int s = (beg < end) ? g_srt[beg] : 0;
    for (int j = beg; j < end; j++) {
        int snext = (j + 1 < end) ? g_srt[j + 1] : 0;
        float e = lrelu(g_ssrc2[s] + sdst);
        float p;
        if (e > m) {
            float sc = __expf(m - e);
            den *= sc; a0 *= sc; a1 *= sc;
            m = e; p = 1.f;
        } else {
            p = __expf(e - m);
        }
        den += p;
        a0 += p * g_h2[s * NC + lane];
        if (lane < 8) a1 += p * g_h2[s * NC + 32 + lane];
        s = snext;
    }
    float inv = 1.f / den;
    float v0 = a0 * inv + b2[lane];
    float v1 = (lane < 8) ? (a1 * inv + b2[32 + lane]) : -INFINITY;
    float mm = fmaxf(v0, v1);
#pragma unroll
    for (int d = 16; d; d >>= 1) mm = fmaxf(mm, __shfl_xor_sync(0xffffffffu, mm, d));
    float se = __expf(v0 - mm) + ((lane < 8) ? __expf(v1 - mm) : 0.f);
#pragma unroll
    for (int d = 16; d; d >>= 1) se += __shfl_xor_sync(0xffffffffu, se, d);
    float ls = mm + logf(se);
    out[i * NC + lane] = v0 - ls;
    if (lane < 8) out[i * NC + 32 + lane] = v1 - ls;
}

// ---- launch: CSR chain forked onto a side stream, overlapped with GEMM1 ----
extern "C" void kernel_launch(void* const* d_in, const int* in_sizes, int n_in,
                              void* d_out, int out_size) {
    const float* x   = (const float*)d_in[0];
    const int*   ei  = (const int*)d_in[1];
    const float* W1  = (const float*)d_in[2];
    const float* as1 = (const float*)d_in[3];
    const float* ad1 = (const float*)d_in[4];
    const float* b1  = (const float*)d_in[5];
    const float* W2  = (const float*)d_in[6];
    const float* as2 = (const float*)d_in[7];
    const float* ad2 = (const float*)d_in[8];
    const float* b2  = (const float*)d_in[9];
    float* out = (float*)d_out;

    static cudaStream_t sB = 0;
    static cudaEvent_t evF = 0, evJ = 0;
    if (!sB) {   // one-time host-side resource setup (first call = correctness run)
        cudaStreamCreateWithFlags(&sB, cudaStreamNonBlocking);
        cudaEventCreateWithFlags(&evF, cudaEventDisableTiming);
        cudaEventCreateWithFlags(&evJ, cudaEventDisableTiming);
        cudaFuncSetAttribute(k_gemm1s, cudaFuncAttributeMaxDynamicSharedMemorySize, G1_SMEM);
    }

    // fork: CSR build on side stream
    cudaEventRecord(evF, 0);
    cudaStreamWaitEvent(sB, evF, 0);
    k_zero<<<(N_NODES + 255) / 256, 256, 0, sB>>>();
    k_hist<<<(NE + 255) / 256, 256, 0, sB>>>(ei);
    k_scan1<<<NSB, SCAN_B, 0, sB>>>();
    k_scan2<<<1, 128, 0, sB>>>();
    k_scan3<<<(N_NODES + 1023) / 1024, 1024, 0, sB>>>();
    k_scatter<<<(NE + 255) / 256, 256, 0, sB>>>(ei);
    cudaEventRecord(evJ, sB);

    // main stream: GEMM1 (+fused s1) overlaps the CSR chain
    k_gemm1s<<<(N_NODES + 127) / 128, 256, G1_SMEM>>>(x, W1, as1, ad1);

    // join, then the dependent chain
    cudaStreamWaitEvent(0, evJ, 0);
    k_agg1<<<(N_NODES * 32 + 255) / 256, 256>>>(b1);
    k_gemm2s<<<(N_NODES + 127) / 128, 256>>>(W2, as2, ad2);
    k_agg2<<<(N_NODES * 32 + 255) / 256, 256>>>(b2, out);
}

// round 17
// speedup vs baseline: 1.3154x; 1.3154x over previous
#include <cuda_runtime.h>
#include <math.h>

#define N_NODES 100000
#define NE      1600000
#define H1H     8
#define C1C     16
#define D1      128
#define NC      40
#define NEG     0.2f

// Scratch: __device__ globals referenced ONLY inside device code (GB300 ATS
// trap: passing the symbol as a kernel arg from host passes the host shadow).
__device__ __align__(256) float g_h1[N_NODES * D1];
__device__ __align__(256) float g_hrelu[N_NODES * D1];
__device__ __align__(256) float g_h2[N_NODES * NC];
__device__ __align__(256) float g_ssrc1[N_NODES * H1H];
__device__ __align__(256) float g_sdst1[N_NODES * H1H];
__device__ __align__(256) float g_ssrc2[N_NODES];
__device__ __align__(256) float g_sdst2[N_NODES];
__device__ __align__(256) int   g_deg[N_NODES];
__device__ __align__(256) int   g_cur[N_NODES];
__device__ __align__(256) int   g_off[N_NODES + 1];
__device__ __align__(256) int   g_srt[NE];

#define SCAN_B 1024
#define NSB ((N_NODES + SCAN_B - 1) / SCAN_B)   /* 98 */
__device__ __align__(256) int g_part[NSB];

__device__ __forceinline__ float lrelu(float x) { return x > 0.f ? x : NEG * x; }

// ---- CSR build (edge_index: int32 planar) ----
__global__ void k_zero() {
    int i = blockIdx.x * blockDim.x + threadIdx.x;
    if (i < N_NODES) { g_deg[i] = 0; g_cur[i] = 0; }
}
__global__ void k_hist(const int* __restrict__ ei) {
    int e = blockIdx.x * blockDim.x + threadIdx.x;
    if (e < NE) atomicAdd(&g_deg[ei[NE + e]], 1);
}
__global__ void k_scan1() {
    __shared__ int s[SCAN_B];
    int t = threadIdx.x, i = blockIdx.x * SCAN_B + t;
    int v = (i < N_NODES) ? g_deg[i] : 0;
    s[t] = v; __syncthreads();
    for (int d = 1; d < SCAN_B; d <<= 1) {
        int x = (t >= d) ? s[t - d] : 0; __syncthreads();
        s[t] += x; __syncthreads();
    }
    if (i < N_NODES) g_off[i] = s[t] - v;
    if (t == SCAN_B - 1) g_part[blockIdx.x] = s[t];
}
__global__ void k_scan2() {
    __shared__ int s[128];
    int t = threadIdx.x;
    int v = (t < NSB) ? g_part[t] : 0;
    s[t] = v; __syncthreads();
    for (int d = 1; d < 128; d <<= 1) {
        int x = (t >= d) ? s[t - d] : 0; __syncthreads();
        s[t] += x; __syncthreads();
    }
    if (t < NSB) g_part[t] = s[t] - v;
}
__global__ void k_scan3() {
    int i = blockIdx.x * blockDim.x + threadIdx.x;
    if (i < N_NODES) g_off[i] += g_part[i >> 10];
    if (i == 0) g_off[N_NODES] = NE;
}
__global__ void k_scatter(const int* __restrict__ ei) {
    int e = blockIdx.x * blockDim.x + threadIdx.x;
    if (e < NE) {
        int d = ei[NE + e];
        int pos = g_off[d] + atomicAdd(&g_cur[d], 1);
        g_srt[pos] = ei[e];
    }
}

// ---- GEMM1 (BK=32, static smem — proven R13 version) + fused s1 logits ----
__global__ void k_gemm1s(const float* __restrict__ A, const float* __restrict__ B,
                         const float* __restrict__ as1, const float* __restrict__ ad1) {
    __shared__ float As[32][132];   // [kk][row]
    __shared__ float Bs[32][132];   // [kk][col]
    int tid = threadIdx.x, tx = tid & 15, ty = tid >> 4;
    int row0 = blockIdx.x * 128, r0 = ty * 8, c0 = tx * 8;
    float acc[8][8];
#pragma unroll
    for (int i = 0; i < 8; i++)
#pragma unroll
        for (int j = 0; j < 8; j++) acc[i][j] = 0.f;

    for (int kb = 0; kb < 128; kb += 32) {
#pragma unroll
        for (int q = 0; q < 4; q++) {
            int f = tid + 256 * q;
            int r = f >> 3, c4 = f & 7;
            int row = row0 + r;
            float4 v = (row < N_NODES)
                       ? *(const float4*)&A[row * 128 + kb + c4 * 4]
                       : make_float4(0.f, 0.f, 0.f, 0.f);
            As[c4 * 4 + 0][r] = v.x;
            As[c4 * 4 + 1][r] = v.y;
            As[c4 * 4 + 2][r] = v.z;
            As[c4 * 4 + 3][r] = v.w;
        }
#pragma unroll
        for (int q = 0; q < 4; q++) {
            int f = tid + 256 * q;
            int kk = f >> 5, c4 = f & 31;
            float4 v = *(const float4*)&B[(kb + kk) * 128 + c4 * 4];
            *(float4*)&Bs[kk][c4 * 4] = v;
        }
        __syncthreads();
#pragma unroll
        for (int kk = 0; kk < 32; kk++) {
            float a[8], b[8];
#pragma unroll
            for (int i = 0; i < 8; i++) a[i] = As[kk][r0 + i];
#pragma unroll
            for (int j = 0; j < 8; j++) b[j] = Bs[kk][c0 + j];
#pragma unroll
            for (int i = 0; i < 8; i++)
#pragma unroll
                for (int j = 0; j < 8; j++) acc[i][j] += a[i] * b[j];
        }
        __syncthreads();
    }

    int h = tx >> 1;
    int cb = h * C1C + (tx & 1) * 8;
    float av[8], dv[8];
#pragma unroll
    for (int j = 0; j < 8; j++) { av[j] = as1[cb + j]; dv[j] = ad1[cb + j]; }

#pragma unroll
    for (int i = 0; i < 8; i++) {
        int row = row0 + r0 + i;
        if (row >= N_NODES) continue;
        *(float4*)&g_h1[row * 128 + c0]     = make_float4(acc[i][0], acc[i][1], acc[i][2], acc[i][3]);
        *(float4*)&g_h1[row * 128 + c0 + 4] = make_float4(acc[i][4], acc[i][5], acc[i][6], acc[i][7]);
        float ps = 0.f, pd = 0.f;
#pragma unroll
        for (int j = 0; j < 8; j++) { ps += acc[i][j] * av[j]; pd += acc[i][j] * dv[j]; }
        ps += __shfl_xor_sync(0xffffffffu, ps, 1);
        pd += __shfl_xor_sync(0xffffffffu, pd, 1);
        if ((tx & 1) == 0) {
            g_ssrc1[row * H1H + h] = ps;
            g_sdst1[row * H1H + h] = pd;
        }
    }
}

// ---- GEMM2 + fused s2 logits ----
__global__ void k_gemm2s(const float* __restrict__ B,
                         const float* __restrict__ as2, const float* __restrict__ ad2) {
    __shared__ float As[16][132];
    __shared__ float Bs[16][48];
    int tid = threadIdx.x, tx = tid & 15, ty = tid >> 4;
    int row0 = blockIdx.x * 128, r0 = ty * 8;
    float acc[8][3];
#pragma unroll
    for (int i = 0; i < 8; i++)
#pragma unroll
        for (int j = 0; j < 3; j++) acc[i][j] = 0.f;
    for (int kb = 0; kb < 128; kb += 16) {
        for (int l = tid; l < 2048; l += 256) {
            int r = l >> 4, kk = l & 15, row = row0 + r;
            As[kk][r] = (row < N_NODES) ? g_hrelu[row * 128 + kb + kk] : 0.f;
        }
        for (int l = tid; l < 640; l += 256) {
            int kk = l / 40, col = l % 40;
            Bs[kk][col] = B[(kb + kk) * 40 + col];
        }
        __syncthreads();
#pragma unroll
        for (int kk = 0; kk < 16; kk++) {
            float a[8];
#pragma unroll
            for (int i = 0; i < 8; i++) a[i] = As[kk][r0 + i];
            float b0 = Bs[kk][tx], b1 = Bs[kk][tx + 16], b2 = (tx < 8) ? Bs[kk][tx + 32] : 0.f;
#pragma unroll
            for (int i = 0; i < 8; i++) {
                acc[i][0] += a[i] * b0; acc[i][1] += a[i] * b1; acc[i][2] += a[i] * b2;
            }
        }
        __syncthreads();
    }
    float a0 = as2[tx], a1 = as2[tx + 16], a2 = (tx < 8) ? as2[tx + 32] : 0.f;
    float d0 = ad2[tx], d1 = ad2[tx + 16], d2 = (tx < 8) ? ad2[tx + 32] : 0.f;
#pragma unroll
    for (int i = 0; i < 8; i++) {
        int row = row0 + r0 + i;
        if (row >= N_NODES) continue;
        g_h2[row * 40 + tx] = acc[i][0];
        g_h2[row * 40 + tx + 16] = acc[i][1];
        if (tx < 8) g_h2[row * 40 + tx + 32] = acc[i][2];
        float ps = acc[i][0] * a0 + acc[i][1] * a1 + acc[i][2] * a2;
        float pd = acc[i][0] * d0 + acc[i][1] * d1 + acc[i][2] * d2;
#pragma unroll
        for (int o = 8; o; o >>= 1) {
            ps += __shfl_xor_sync(0xffffffffu, ps, o);
            pd += __shfl_xor_sync(0xffffffffu, pd, o);
        }
        if (tx == 0) { g_ssrc2[row] = ps; g_sdst2[row] = pd; }
    }
}

// ---- layer1 aggregation: warp/node, single-pass online softmax ----
__global__ void k_agg1(const float* __restrict__ b1) {
    int warp = (blockIdx.x * blockDim.x + threadIdx.x) >> 5;
    int lane = threadIdx.x & 31;
    if (warp >= N_NODES) return;
    int i = warp, h = lane >> 2;
    float sdst = g_sdst1[i * H1H + h];
    float m = lrelu(g_ssrc1[i * H1H + h] + sdst);
    int beg = g_off[i], end = g_off[i + 1];
    const float4* hp = (const float4*)g_h1;
    float den = 1.f;
    float4 acc = hp[i * 32 + lane];
    int s = (beg < end) ? g_srt[beg] : 0;
    for (int j = beg; j < end; j++) {
        int snext = (j + 1 < end) ? g_srt[j + 1] : 0;
        float e = lrelu(g_ssrc1[s * H1H + h] + sdst);
        float p;
        if (e > m) {
            float sc = __expf(m - e);
            den *= sc;
            acc.x *= sc; acc.y *= sc; acc.z *= sc; acc.w *= sc;
            m = e; p = 1.f;
        } else {
            p = __expf(e - m);
        }
        float4 w = hp[s * 32 + lane];
        den += p;
        acc.x += p * w.x; acc.y += p * w.y; acc.z += p * w.z; acc.w += p * w.w;
        s = snext;
    }
    float inv = 1.f / den;
    float4 o;
    o.x = fmaxf(acc.x * inv + b1[lane * 4 + 0], 0.f);
    o.y = fmaxf(acc.y * inv + b1[lane * 4 + 1], 0.f);
    o.z = fmaxf(acc.z * inv + b1[lane * 4 + 2], 0.f);
    o.w = fmaxf(acc.w * inv + b1[lane * 4 + 3], 0.f);
    ((float4*)g_hrelu)[i * 32 + lane] = o;
}

// ---- layer2 aggregation (online softmax) + log_softmax ----
__global__ void k_agg2(const float* __restrict__ b2, float* __restrict__ out) {
    int warp = (blockIdx.x * blockDim.x + threadIdx.x) >> 5;
    int lane = threadIdx.x & 31;
    if (warp >= N_NODES) return;
    int i = warp;
    float sdst = g_sdst2[i];
    float m = lrelu(g_ssrc2[i] + sdst);
    int beg = g_off[i], end = g_off[i + 1];
    float den = 1.f;
    float a0 = g_h2[i * NC + lane];
    float a1 = (lane < 8) ? g_h2[i * NC + 32 + lane] : 0.f;
    int s = (beg < end) ? g_srt[beg] : 0;
    for (int j = beg; j < end; j++) {
        int snext = (j + 1 < end) ? g_srt[j + 1] : 0;
        float e = lrelu(g_ssrc2[s] + sdst);
        float p;
        if (e > m) {
            float sc = __expf(m - e);
            den *= sc; a0 *= sc; a1 *= sc;
            m = e; p = 1.f;
        } else {
            p = __expf(e - m);
        }
        den += p;
        a0 += p * g_h2[s * NC + lane];
        if (lane < 8) a1 += p * g_h2[s * NC + 32 + lane];
        s = snext;
    }
    float inv = 1.f / den;
    float v0 = a0 * inv + b2[lane];
    float v1 = (lane < 8) ? (a1 * inv + b2[32 + lane]) : -INFINITY;
    float mm = fmaxf(v0, v1);
#pragma unroll
    for (int d = 16; d; d >>= 1) mm = fmaxf(mm, __shfl_xor_sync(0xffffffffu, mm, d));
    float se = __expf(v0 - mm) + ((lane < 8) ? __expf(v1 - mm) : 0.f);
#pragma unroll
    for (int d = 16; d; d >>= 1) se += __shfl_xor_sync(0xffffffffu, se, d);
    float ls = mm + logf(se);
    out[i * NC + lane] = v0 - ls;
    if (lane < 8) out[i * NC + 32 + lane] = v1 - ls;
}

// ---- launch: CSR chain forked onto side stream, overlapped with GEMM1 ----
extern "C" void kernel_launch(void* const* d_in, const int* in_sizes, int n_in,
                              void* d_out, int out_size) {
    const float* x   = (const float*)d_in[0];
    const int*   ei  = (const int*)d_in[1];
    const float* W1  = (const float*)d_in[2];
    const float* as1 = (const float*)d_in[3];
    const float* ad1 = (const float*)d_in[4];
    const float* b1  = (const float*)d_in[5];
    const float* W2  = (const float*)d_in[6];
    const float* as2 = (const float*)d_in[7];
    const float* ad2 = (const float*)d_in[8];
    const float* b2  = (const float*)d_in[9];
    float* out = (float*)d_out;

    static cudaStream_t sB = 0;
    static cudaEvent_t evF = 0, evJ = 0;
    if (!sB) {   // one-time host-side resource setup (first call = correctness run)
        cudaStreamCreateWithFlags(&sB, cudaStreamNonBlocking);
        cudaEventCreateWithFlags(&evF, cudaEventDisableTiming);
        cudaEventCreateWithFlags(&evJ, cudaEventDisableTiming);
    }

    // fork: CSR build on side stream
    cudaEventRecord(evF, 0);
    cudaStreamWaitEvent(sB, evF, 0);
    k_zero<<<(N_NODES + 255) / 256, 256, 0, sB>>>();
    k_hist<<<(NE + 255) / 256, 256, 0, sB>>>(ei);
    k_scan1<<<NSB, SCAN_B, 0, sB>>>();
    k_scan2<<<1, 128, 0, sB>>>();
    k_scan3<<<(N_NODES + 1023) / 1024, 1024, 0, sB>>>();
    k_scatter<<<(NE + 255) / 256, 256, 0, sB>>>(ei);
    cudaEventRecord(evJ, sB);

    // main stream: GEMM1 (+fused s1) overlaps the CSR chain
    k_gemm1s<<<(N_NODES + 127) / 128, 256>>>(x, W1, as1, ad1);

    // join, then the dependent chain
    cudaStreamWaitEvent(0, evJ, 0);
    k_agg1<<<(N_NODES * 32 + 255) / 256, 256>>>(b1);
    k_gemm2s<<<(N_NODES + 127) / 128, 256>>>(W2, as2, ad2);
    k_agg2<<<(N_NODES * 32 + 255) / 256, 256>>>(b2, out);
}